// round 4
// baseline (speedup 1.0000x reference)
#include <cuda_runtime.h>
#include <cuda_bf16.h>
#include <cuda_fp16.h>
#include <math.h>

// Problem constants
constexpr int B   = 16;
constexpr int H   = 8;
constexpr int N1  = 256;
constexpr int N2  = 576;
constexpr int HD  = 64;
constexpr int DIM = 512;
constexpr int BH  = B * H;       // 128
constexpr int ITERS = 100;

typedef unsigned long long u64;
typedef unsigned int u32;

// ---- packed f32x2 helpers (sm_103a FFMA2; ptxas never auto-fuses) ----
__device__ __forceinline__ u64 ffma2(u64 a, u64 b, u64 c) {
    u64 d; asm("fma.rn.f32x2 %0,%1,%2,%3;" : "=l"(d) : "l"(a), "l"(b), "l"(c)); return d;
}
__device__ __forceinline__ u64 pack2(float x, float y) {
    u64 d; asm("mov.b64 %0,{%1,%2};" : "=l"(d) : "f"(x), "f"(y)); return d;
}
__device__ __forceinline__ float2 unpack2(u64 d) {
    float2 r; asm("mov.b64 {%0,%1},%2;" : "=f"(r.x), "=f"(r.y) : "l"(d)); return r;
}

// Static scratch (no runtime allocation allowed)
__device__ float g_tq[B * N1 * DIM];
__device__ float g_tk[B * N2 * DIM];
__device__ float g_tv[B * N2 * DIM];
__device__ float g_q[BH * N1 * HD];
__device__ float g_k[BH * N2 * HD];
__device__ float g_v[BH * N2 * HD];
__device__ float g_sim[(size_t)BH * N1 * N2];            // fp32 sim (exact)
__device__ __half g_A16[(size_t)BH * N1 * N2];           // fp16 shifted Gibbs kernel e^(20 sim - 9)
__device__ float g_alpha[BH * N1];
__device__ float g_beta[BH * N2];
__device__ float g_ctx[B * N1 * DIM];

// ---------------------------------------------------------------------------
// fp32 GEMM, 128x128 tile, 256 threads, 8x8/thread, FFMA2 inner product.
// Broadcast operand (X) stored DUPLICATED in smem so LDS.64 yields the f32x2
// broadcast with zero MOVs; pair operand (W) read directly as u64 pairs.
// out[M,N] = X[M,K] @ W[N,K]^T + bias[N].  M,N,K multiples of 128/16.
// ---------------------------------------------------------------------------
__global__ __launch_bounds__(256) void gemm128_kernel(
    const float* __restrict__ X, const float* __restrict__ W,
    const float* __restrict__ bias, float* __restrict__ out,
    int M, int N, int K)
{
    __shared__ __align__(16) float Xs2[16][264];   // duplicated: [k][2*m]
    __shared__ __align__(16) float Ws[16][132];
    const int tid = threadIdx.x;
    const int tx = tid & 15, ty = tid >> 4;
    const int bm = blockIdx.y * 128, bn = blockIdx.x * 128;
    const int lr = tid >> 1;            // 0..127
    const int lc = (tid & 1) * 8;       // 0 or 8

    u64 acc[2][2][4][2];
#pragma unroll
    for (int iq = 0; iq < 2; iq++)
#pragma unroll
        for (int jq = 0; jq < 2; jq++)
#pragma unroll
            for (int i = 0; i < 4; i++) { acc[iq][jq][i][0] = 0ull; acc[iq][jq][i][1] = 0ull; }

    const float* Xp = X + (size_t)(bm + lr) * K + lc;
    const float* Wp = W + (size_t)(bn + lr) * K + lc;

    for (int k0 = 0; k0 < K; k0 += 16) {
        float4 x0 = *(const float4*)(Xp + k0);
        float4 x1 = *(const float4*)(Xp + k0 + 4);
        float4 w0 = *(const float4*)(Wp + k0);
        float4 w1 = *(const float4*)(Wp + k0 + 4);
        // duplicated X writes (STS.64 pairs)
        *(u64*)&Xs2[lc + 0][2 * lr] = pack2(x0.x, x0.x);
        *(u64*)&Xs2[lc + 1][2 * lr] = pack2(x0.y, x0.y);
        *(u64*)&Xs2[lc + 2][2 * lr] = pack2(x0.z, x0.z);
        *(u64*)&Xs2[lc + 3][2 * lr] = pack2(x0.w, x0.w);
        *(u64*)&Xs2[lc + 4][2 * lr] = pack2(x1.x, x1.x);
        *(u64*)&Xs2[lc + 5][2 * lr] = pack2(x1.y, x1.y);
        *(u64*)&Xs2[lc + 6][2 * lr] = pack2(x1.z, x1.z);
        *(u64*)&Xs2[lc + 7][2 * lr] = pack2(x1.w, x1.w);
        Ws[lc + 0][lr] = w0.x; Ws[lc + 1][lr] = w0.y; Ws[lc + 2][lr] = w0.z; Ws[lc + 3][lr] = w0.w;
        Ws[lc + 4][lr] = w1.x; Ws[lc + 5][lr] = w1.y; Ws[lc + 6][lr] = w1.z; Ws[lc + 7][lr] = w1.w;
        __syncthreads();
#pragma unroll
        for (int kk = 0; kk < 16; kk++) {
            u64 a[2][4];
#pragma unroll
            for (int iq = 0; iq < 2; iq++)
#pragma unroll
                for (int i = 0; i < 4; i++)
                    a[iq][i] = *(const u64*)&Xs2[kk][2 * (iq * 64 + (ty << 2) + i)];
            const u64* bw0 = (const u64*)&Ws[kk][(tx << 2)];
            const u64* bw1 = (const u64*)&Ws[kk][64 + (tx << 2)];
            u64 b[2][2] = {{bw0[0], bw0[1]}, {bw1[0], bw1[1]}};
#pragma unroll
            for (int iq = 0; iq < 2; iq++)
#pragma unroll
                for (int i = 0; i < 4; i++)
#pragma unroll
                    for (int jq = 0; jq < 2; jq++) {
                        acc[iq][jq][i][0] = ffma2(a[iq][i], b[jq][0], acc[iq][jq][i][0]);
                        acc[iq][jq][i][1] = ffma2(a[iq][i], b[jq][1], acc[iq][jq][i][1]);
                    }
        }
        __syncthreads();
    }
#pragma unroll
    for (int iq = 0; iq < 2; iq++)
#pragma unroll
        for (int i = 0; i < 4; i++) {
            int r = bm + iq * 64 + ty * 4 + i;
#pragma unroll
            for (int jq = 0; jq < 2; jq++) {
                int c = bn + jq * 64 + tx * 4;
                float2 p0 = unpack2(acc[iq][jq][i][0]);
                float2 p1 = unpack2(acc[iq][jq][i][1]);
                float4 o = make_float4(p0.x + bias[c], p0.y + bias[c + 1],
                                       p1.x + bias[c + 2], p1.y + bias[c + 3]);
                *(float4*)(out + (size_t)r * N + c) = o;
            }
        }
}

// ---------------------------------------------------------------------------
// Transpose [B, Nn, H*64] -> [B, H, Nn, 64], optional L2 norm (clamped)
// ---------------------------------------------------------------------------
__global__ void qk_transnorm_kernel(const float* __restrict__ src,
                                    float* __restrict__ dst, int Nn, int do_norm)
{
    int gw = (int)((blockIdx.x * blockDim.x + threadIdx.x) >> 5);
    int lane = threadIdx.x & 31;
    int total = B * Nn * H;
    if (gw >= total) return;
    int h = gw % H;
    int n = (gw / H) % Nn;
    int b = gw / (H * Nn);
    const float* sp = src + (size_t)(b * Nn + n) * DIM + h * HD;
    float2 x = *(const float2*)(sp + lane * 2);
    float s = 1.f;
    if (do_norm) {
        float ss = x.x * x.x + x.y * x.y;
#pragma unroll
        for (int o = 16; o > 0; o >>= 1) ss += __shfl_xor_sync(0xffffffffu, ss, o);
        s = 1.0f / fmaxf(sqrtf(ss), 1e-12f);
    }
    float* dp = dst + (size_t)((b * H + h) * Nn + n) * HD;
    *(float2*)(dp + lane * 2) = make_float2(x.x * s, x.y * s);
}

// ---------------------------------------------------------------------------
// sim = q.k (beta_t=1); store fp32 sim and fp16 shifted A = exp(20*sim - 9).
// Q duplicated in smem (broadcast side), K read as natural u64 pairs.
// Smem exactly 48KB: Qs2[64][128] + Ks[64][64].
// ---------------------------------------------------------------------------
__global__ __launch_bounds__(256) void sim_kernel(
    const float* __restrict__ q, const float* __restrict__ k,
    float* __restrict__ simo, __half* __restrict__ Ao)
{
    __shared__ __align__(16) float Qs2[64][128];   // [kk][2*i] duplicated
    __shared__ __align__(16) float Ks[64][64];     // [kk][j]
    int bh = blockIdx.z;
    int i0 = blockIdx.y * 64, j0 = blockIdx.x * 64;
    const float* qp = q + (size_t)bh * N1 * HD;
    const float* kp = k + (size_t)bh * N2 * HD;
    int tid = threadIdx.x;
    int tx = tid & 15, ty = tid >> 4;
    int lr = tid >> 2;
#pragma unroll
    for (int it = 0; it < 4; it++) {
        int lc = (((tid & 3) + (it << 2)) << 2);
        float4 qv = *(const float4*)(qp + (size_t)(i0 + lr) * HD + lc);
        *(u64*)&Qs2[lc + 0][2 * lr] = pack2(qv.x, qv.x);
        *(u64*)&Qs2[lc + 1][2 * lr] = pack2(qv.y, qv.y);
        *(u64*)&Qs2[lc + 2][2 * lr] = pack2(qv.z, qv.z);
        *(u64*)&Qs2[lc + 3][2 * lr] = pack2(qv.w, qv.w);
        float4 kv = *(const float4*)(kp + (size_t)(j0 + lr) * HD + lc);
        Ks[lc + 0][lr] = kv.x; Ks[lc + 1][lr] = kv.y; Ks[lc + 2][lr] = kv.z; Ks[lc + 3][lr] = kv.w;
    }
    __syncthreads();
    u64 acc2[4][2];
#pragma unroll
    for (int i = 0; i < 4; i++) { acc2[i][0] = 0ull; acc2[i][1] = 0ull; }
#pragma unroll 8
    for (int kk = 0; kk < 64; kk++) {
        u64 a[4];
#pragma unroll
        for (int i = 0; i < 4; i++) a[i] = *(const u64*)&Qs2[kk][2 * ((ty << 2) + i)];
        const u64* bw = (const u64*)&Ks[kk][tx << 2];
        u64 b01 = bw[0], b23 = bw[1];
#pragma unroll
        for (int i = 0; i < 4; i++) {
            acc2[i][0] = ffma2(a[i], b01, acc2[i][0]);
            acc2[i][1] = ffma2(a[i], b23, acc2[i][1]);
        }
    }
    size_t base = (size_t)bh * N1 * N2;
#pragma unroll
    for (int i = 0; i < 4; i++) {
        size_t idx = base + (size_t)(i0 + (ty << 2) + i) * N2 + (j0 + (tx << 2));
        float2 p0 = unpack2(acc2[i][0]);
        float2 p1 = unpack2(acc2[i][1]);
        *(float4*)(simo + idx) = make_float4(p0.x, p0.y, p1.x, p1.y);
        __half2* A2 = (__half2*)(Ao + idx);
        A2[0] = __floats2half2_rn(__expf(fmaf(p0.x, 20.0f, -9.0f)),
                                  __expf(fmaf(p0.y, 20.0f, -9.0f)));
        A2[1] = __floats2half2_rn(__expf(fmaf(p1.x, 20.0f, -9.0f)),
                                  __expf(fmaf(p1.y, 20.0f, -9.0f)));
    }
}

// ---------------------------------------------------------------------------
// Sinkhorn (scaled domain), fp16 shifted A, one CTA per bh slice, 512 threads.
// Single pass per iteration computes A.beta (rows) and A^T.alpha (cols)
// with the OLD (alpha,beta) -- algebraically identical to the reference
// (uniform scale e^11 of A is absorbed by scale-invariance of T).
// Early-exit when max relative change < 1e-6 (below fp32 significance).
// ---------------------------------------------------------------------------
__global__ __launch_bounds__(512) void sinkhorn_kernel(
    const __half* __restrict__ A16, float* __restrict__ alpha_out,
    float* __restrict__ beta_out)
{
    __shared__ __align__(16) float s_alpha[N1];
    __shared__ __align__(16) float s_beta[N2];
    __shared__ __align__(16) float s_r[N1];
    __shared__ __align__(16) float s_cpart[16][N2];
    __shared__ float s_wmax[16];

    int bh = blockIdx.x;
    const u32* A = (const u32*)(A16 + (size_t)bh * N1 * N2);  // 288 u32 per row
    int tid = threadIdx.x, lane = tid & 31, w = tid >> 5;

    for (int i = tid; i < N1; i += 512) s_alpha[i] = 1.f;
    for (int j = tid; j < N2; j += 512) s_beta[j] = 1.f;
    __syncthreads();

    const float MU = 1.0f / 256.0f + 1e-8f;
    const float NU = 1.0f / 576.0f + 1e-8f;

#pragma unroll 1
    for (int it = 0; it < ITERS; it++) {
        u64 pb[9], pc[9];
        const u64* sb2 = (const u64*)s_beta;
#pragma unroll
        for (int t = 0; t < 9; t++) { pb[t] = sb2[lane + 32 * t]; pc[t] = 0ull; }

#pragma unroll 1
        for (int rr = 0; rr < 16; rr++) {
            int i = w * 16 + rr;
            float ai = s_alpha[i];
            u64 ad = pack2(ai, ai);
            u64 accr2 = 0ull;
            const u32* row = A + i * 288 + lane;
#pragma unroll
            for (int t = 0; t < 9; t++) {
                u32 x = row[32 * t];
                __half2 h2 = *reinterpret_cast<const __half2*>(&x);
                float2 f = __half22float2(h2);       // HW cvt handles subnormal tail
                u64 a2 = pack2(f.x, f.y);
                accr2 = ffma2(a2, pb[t], accr2);     // row sum   (A beta)
                pc[t] = ffma2(a2, ad, pc[t]);        // col parts (A^T alpha)
            }
            float2 ar = unpack2(accr2);
            float accr = ar.x + ar.y;
#pragma unroll
            for (int o = 16; o > 0; o >>= 1) accr += __shfl_xor_sync(0xffffffffu, accr, o);
            if (lane == 0) s_r[i] = accr;
        }
        u64* cp2 = (u64*)&s_cpart[w][0];
#pragma unroll
        for (int t = 0; t < 9; t++) cp2[lane + 32 * t] = pc[t];
        __syncthreads();

        float mx = 0.f;
        if (tid < N1) {
            float na = MU / s_r[tid];
            mx = fabsf(na - s_alpha[tid]) / na;
            s_alpha[tid] = na;
        }
        for (int j = tid; j < N2; j += 512) {
            float sc = 0.f;
#pragma unroll
            for (int ww = 0; ww < 16; ww++) sc += s_cpart[ww][j];
            float nb = NU / sc;
            mx = fmaxf(mx, fabsf(nb - s_beta[j]) / nb);
            s_beta[j] = nb;
        }
#pragma unroll
        for (int o = 16; o > 0; o >>= 1) mx = fmaxf(mx, __shfl_xor_sync(0xffffffffu, mx, o));
        if (lane == 0) s_wmax[w] = mx;
        __syncthreads();
        float m = 0.f;
#pragma unroll
        for (int ww = 0; ww < 16; ww++) m = fmaxf(m, s_wmax[ww]);
        if (m < 1e-6f) break;   // converged to fp32 significance; rest are no-ops
    }

    for (int i = tid; i < N1; i += 512) alpha_out[bh * N1 + i] = s_alpha[i];
    for (int j = tid; j < N2; j += 512) beta_out[bh * N2 + j] = s_beta[j];
}

// ---------------------------------------------------------------------------
// ctx = (N1*N2 * sim * exp(20*sim-9) * alpha_n * beta_m) @ v
// (fp32 A recomputed with the SAME shift as Sinkhorn's -> consistent T).
// Score tile duplicated in smem (broadcast side). Smem exactly 48KB.
// ---------------------------------------------------------------------------
__global__ __launch_bounds__(256) void av_kernel(
    const float* __restrict__ sim_all, const float* __restrict__ v_all,
    const float* __restrict__ alpha, const float* __restrict__ beta,
    float* __restrict__ ctx)
{
    __shared__ __align__(16) float Ss2[64][128];   // [m][2*n] duplicated
    __shared__ __align__(16) float Vs[64][64];     // [m][c]
    int bh = blockIdx.y;
    int n0 = blockIdx.x * 64;
    const float* simp = sim_all + (size_t)bh * N1 * N2;
    const float* vp   = v_all   + (size_t)bh * N2 * HD;
    int tid = threadIdx.x, tx = tid & 15, ty = tid >> 4;
    int lr = tid >> 2;

    const float an = alpha[bh * N1 + n0 + lr] * 147456.0f;  // fold N1*N2; per-thread scalar
    const float* betap = beta + bh * N2;

    u64 acc2[4][2];
#pragma unroll
    for (int i = 0; i < 4; i++) { acc2[i][0] = 0ull; acc2[i][1] = 0ull; }

    for (int m0 = 0; m0 < N2; m0 += 64) {
        __syncthreads();          // previous tile's compute done before overwrite
#pragma unroll
        for (int it = 0; it < 4; it++) {
            int lc = (((tid & 3) + (it << 2)) << 2);
            size_t idx = (size_t)(n0 + lr) * N2 + m0 + lc;
            float4 sv = *(const float4*)(simp + idx);
            float4 bv = *(const float4*)(betap + m0 + lc);
            float s0 = sv.x * __expf(fmaf(sv.x, 20.f, -9.f)) * an * bv.x;
            float s1 = sv.y * __expf(fmaf(sv.y, 20.f, -9.f)) * an * bv.y;
            float s2 = sv.z * __expf(fmaf(sv.z, 20.f, -9.f)) * an * bv.z;
            float s3 = sv.w * __expf(fmaf(sv.w, 20.f, -9.f)) * an * bv.w;
            *(u64*)&Ss2[lc + 0][2 * lr] = pack2(s0, s0);
            *(u64*)&Ss2[lc + 1][2 * lr] = pack2(s1, s1);
            *(u64*)&Ss2[lc + 2][2 * lr] = pack2(s2, s2);
            *(u64*)&Ss2[lc + 3][2 * lr] = pack2(s3, s3);
            float4 vv = *(const float4*)(vp + (size_t)(m0 + lr) * HD + lc);
            Vs[lr][lc + 0] = vv.x; Vs[lr][lc + 1] = vv.y;
            Vs[lr][lc + 2] = vv.z; Vs[lr][lc + 3] = vv.w;
        }
        __syncthreads();
#pragma unroll 8
        for (int kk = 0; kk < 64; kk++) {
            u64 a[4];
#pragma unroll
            for (int i = 0; i < 4; i++) a[i] = *(const u64*)&Ss2[kk][2 * ((ty << 2) + i)];
            const u64* bw = (const u64*)&Vs[kk][tx << 2];
            u64 b01 = bw[0], b23 = bw[1];
#pragma unroll
            for (int i = 0; i < 4; i++) {
                acc2[i][0] = ffma2(a[i], b01, acc2[i][0]);
                acc2[i][1] = ffma2(a[i], b23, acc2[i][1]);
            }
        }
    }
    int b = bh >> 3, h = bh & 7;
#pragma unroll
    for (int i = 0; i < 4; i++) {
        float2 p0 = unpack2(acc2[i][0]);
        float2 p1 = unpack2(acc2[i][1]);
        float* dst = ctx + (size_t)(b * N1 + n0 + (ty << 2) + i) * DIM + h * HD + (tx << 2);
        *(float4*)dst = make_float4(p0.x, p0.y, p1.x, p1.y);
    }
}

// ---------------------------------------------------------------------------
// In-place row L2 normalization (plain divide): rows of 512 floats
// ---------------------------------------------------------------------------
__global__ __launch_bounds__(128) void norm_rows_kernel(float* __restrict__ out)
{
    __shared__ float red[4];
    int row = blockIdx.x;
    float4* p = (float4*)(out + (size_t)row * DIM);
    int tid = threadIdx.x;
    float4 v = p[tid];
    float ss = v.x * v.x + v.y * v.y + v.z * v.z + v.w * v.w;
#pragma unroll
    for (int o = 16; o > 0; o >>= 1) ss += __shfl_xor_sync(0xffffffffu, ss, o);
    if ((tid & 31) == 0) red[tid >> 5] = ss;
    __syncthreads();
    float tot = red[0] + red[1] + red[2] + red[3];
    float inv = 1.0f / sqrtf(tot);
    v.x *= inv; v.y *= inv; v.z *= inv; v.w *= inv;
    p[tid] = v;
}

// ---------------------------------------------------------------------------
extern "C" void kernel_launch(void* const* d_in, const int* in_sizes, int n_in,
                              void* d_out, int out_size)
{
    (void)in_sizes; (void)n_in; (void)out_size;
    const float* F_t = (const float*)d_in[0];
    const float* F_s = (const float*)d_in[1];
    const float* Wq  = (const float*)d_in[2];
    const float* bq  = (const float*)d_in[3];
    const float* Wk  = (const float*)d_in[4];
    const float* bk  = (const float*)d_in[5];
    const float* Wv  = (const float*)d_in[6];
    const float* bv  = (const float*)d_in[7];
    const float* Wp  = (const float*)d_in[8];
    const float* bp  = (const float*)d_in[9];
    float* out = (float*)d_out;

    float *tq, *tk, *tv, *q, *k, *v, *simb, *alpha, *beta, *ctx;
    __half* A16;
    cudaGetSymbolAddress((void**)&tq, g_tq);
    cudaGetSymbolAddress((void**)&tk, g_tk);
    cudaGetSymbolAddress((void**)&tv, g_tv);
    cudaGetSymbolAddress((void**)&q, g_q);
    cudaGetSymbolAddress((void**)&k, g_k);
    cudaGetSymbolAddress((void**)&v, g_v);
    cudaGetSymbolAddress((void**)&simb, g_sim);
    cudaGetSymbolAddress((void**)&A16, g_A16);
    cudaGetSymbolAddress((void**)&alpha, g_alpha);
    cudaGetSymbolAddress((void**)&beta, g_beta);
    cudaGetSymbolAddress((void**)&ctx, g_ctx);

    // 1) QKV projections (conv1d k=1 == pointwise linear), 128x128 FFMA2 GEMM
    gemm128_kernel<<<dim3(DIM / 128, B * N1 / 128), 256>>>(F_t, Wq, bq, tq, B * N1, DIM, DIM);
    gemm128_kernel<<<dim3(DIM / 128, B * N2 / 128), 256>>>(F_s, Wk, bk, tk, B * N2, DIM, DIM);
    gemm128_kernel<<<dim3(DIM / 128, B * N2 / 128), 256>>>(F_s, Wv, bv, tv, B * N2, DIM, DIM);

    // 2) transpose to [B,H,Nx,64] (+ l2norm for q,k)
    {
        int warps_q = B * N1 * H;
        int warps_k = B * N2 * H;
        qk_transnorm_kernel<<<(warps_q * 32 + 255) / 256, 256>>>(tq, q, N1, 1);
        qk_transnorm_kernel<<<(warps_k * 32 + 255) / 256, 256>>>(tk, k, N2, 1);
        qk_transnorm_kernel<<<(warps_k * 32 + 255) / 256, 256>>>(tv, v, N2, 0);
    }

    // 3) sim (fp32) + fp16 shifted Gibbs kernel A = exp(20*sim - 9)
    sim_kernel<<<dim3(N2 / 64, N1 / 64, BH), 256>>>(q, k, simb, A16);

    // 4) Sinkhorn iterations (fp16 A, early exit), one CTA per (b,h)
    sinkhorn_kernel<<<BH, 512>>>(A16, alpha, beta);

    // 5) score @ v -> ctx [B*N1, 512]  (fp32 shifted A recomputed from sim)
    av_kernel<<<dim3(N1 / 64, BH), 256>>>(simb, v, alpha, beta, ctx);

    // 6) projection + 7) row normalize (in place in d_out)
    gemm128_kernel<<<dim3(DIM / 128, B * N1 / 128), 256>>>(ctx, Wp, bp, out, B * N1, DIM, DIM);
    norm_rows_kernel<<<B * N1, 128>>>(out);
}

// round 5
// speedup vs baseline: 1.0935x; 1.0935x over previous
#include <cuda_runtime.h>
#include <cuda_fp16.h>
#include <math.h>

// Problem constants
constexpr int B   = 16;
constexpr int H   = 8;
constexpr int N1  = 256;
constexpr int N2  = 576;
constexpr int HD  = 64;
constexpr int DIM = 512;
constexpr int BH  = B * H;       // 128
constexpr int ITERS = 100;

typedef unsigned long long u64;
typedef unsigned int u32;

// ---- packed f32x2 helpers (sm_103a FFMA2; ptxas never auto-fuses) ----
__device__ __forceinline__ u64 ffma2(u64 a, u64 b, u64 c) {
    u64 d; asm("fma.rn.f32x2 %0,%1,%2,%3;" : "=l"(d) : "l"(a), "l"(b), "l"(c)); return d;
}
__device__ __forceinline__ u64 pack2(float x, float y) {
    u64 d; asm("mov.b64 %0,{%1,%2};" : "=l"(d) : "f"(x), "f"(y)); return d;
}
__device__ __forceinline__ float2 unpack2(u64 d) {
    float2 r; asm("mov.b64 {%0,%1},%2;" : "=f"(r.x), "=f"(r.y) : "l"(d)); return r;
}

// Static scratch (no runtime allocation allowed)
__device__ float g_tq[B * N1 * DIM];
__device__ float g_tk[B * N2 * DIM];
__device__ float g_tv[B * N2 * DIM];
__device__ float g_q[BH * N1 * HD];
__device__ float g_k[BH * N2 * HD];
__device__ float g_v[BH * N2 * HD];
__device__ float g_sim[(size_t)BH * N1 * N2];     // fp32 sim (exact)
__device__ __half g_A16[(size_t)BH * N1 * N2];    // fp16 shifted Gibbs kernel e^(20 sim - 9)
__device__ float g_alpha[BH * N1];
__device__ float g_beta[BH * N2];
__device__ float g_ctx[B * N1 * DIM];

// ---------------------------------------------------------------------------
// fp32 GEMM, 128x128 tile, 256 threads, 8x8/thread (2x2 quadrants of 4x4),
// FFMA2 inner product:  out[M,N] = X[M,K] @ W[N,K]^T + bias[N]
// M,N,K multiples of 128/16.  (R3-proven structure.)
// ---------------------------------------------------------------------------
__global__ __launch_bounds__(256) void gemm128_kernel(
    const float* __restrict__ X, const float* __restrict__ W,
    const float* __restrict__ bias, float* __restrict__ out,
    int M, int N, int K)
{
    __shared__ __align__(16) float Xs[16][132];
    __shared__ __align__(16) float Ws[16][132];
    const int tid = threadIdx.x;
    const int tx = tid & 15, ty = tid >> 4;
    const int bm = blockIdx.y * 128, bn = blockIdx.x * 128;
    const int lr = tid >> 1;            // 0..127
    const int lc = (tid & 1) * 8;       // 0 or 8

    u64 acc[2][2][4][2];
#pragma unroll
    for (int iq = 0; iq < 2; iq++)
#pragma unroll
        for (int jq = 0; jq < 2; jq++)
#pragma unroll
            for (int i = 0; i < 4; i++) { acc[iq][jq][i][0] = 0ull; acc[iq][jq][i][1] = 0ull; }

    const float* Xp = X + (size_t)(bm + lr) * K + lc;
    const float* Wp = W + (size_t)(bn + lr) * K + lc;

    for (int k0 = 0; k0 < K; k0 += 16) {
        float4 x0 = *(const float4*)(Xp + k0);
        float4 x1 = *(const float4*)(Xp + k0 + 4);
        float4 w0 = *(const float4*)(Wp + k0);
        float4 w1 = *(const float4*)(Wp + k0 + 4);
        Xs[lc + 0][lr] = x0.x; Xs[lc + 1][lr] = x0.y; Xs[lc + 2][lr] = x0.z; Xs[lc + 3][lr] = x0.w;
        Xs[lc + 4][lr] = x1.x; Xs[lc + 5][lr] = x1.y; Xs[lc + 6][lr] = x1.z; Xs[lc + 7][lr] = x1.w;
        Ws[lc + 0][lr] = w0.x; Ws[lc + 1][lr] = w0.y; Ws[lc + 2][lr] = w0.z; Ws[lc + 3][lr] = w0.w;
        Ws[lc + 4][lr] = w1.x; Ws[lc + 5][lr] = w1.y; Ws[lc + 6][lr] = w1.z; Ws[lc + 7][lr] = w1.w;
        __syncthreads();
#pragma unroll
        for (int kk = 0; kk < 16; kk++) {
            float4 a0 = *(const float4*)&Xs[kk][ty * 4];
            float4 a1 = *(const float4*)&Xs[kk][64 + ty * 4];
            float4 b0 = *(const float4*)&Ws[kk][tx * 4];
            float4 b1 = *(const float4*)&Ws[kk][64 + tx * 4];
            u64 bp[2][2] = {{pack2(b0.x, b0.y), pack2(b0.z, b0.w)},
                            {pack2(b1.x, b1.y), pack2(b1.z, b1.w)}};
            float av[2][4] = {{a0.x, a0.y, a0.z, a0.w}, {a1.x, a1.y, a1.z, a1.w}};
#pragma unroll
            for (int iq = 0; iq < 2; iq++)
#pragma unroll
                for (int i = 0; i < 4; i++) {
                    u64 ad = pack2(av[iq][i], av[iq][i]);
#pragma unroll
                    for (int jq = 0; jq < 2; jq++) {
                        acc[iq][jq][i][0] = ffma2(ad, bp[jq][0], acc[iq][jq][i][0]);
                        acc[iq][jq][i][1] = ffma2(ad, bp[jq][1], acc[iq][jq][i][1]);
                    }
                }
        }
        __syncthreads();
    }
#pragma unroll
    for (int iq = 0; iq < 2; iq++)
#pragma unroll
        for (int i = 0; i < 4; i++) {
            int r = bm + iq * 64 + ty * 4 + i;
#pragma unroll
            for (int jq = 0; jq < 2; jq++) {
                int c = bn + jq * 64 + tx * 4;
                float2 p0 = unpack2(acc[iq][jq][i][0]);
                float2 p1 = unpack2(acc[iq][jq][i][1]);
                float4 o = make_float4(p0.x + bias[c], p0.y + bias[c + 1],
                                       p1.x + bias[c + 2], p1.y + bias[c + 3]);
                *(float4*)(out + (size_t)r * N + c) = o;
            }
        }
}

// ---------------------------------------------------------------------------
// Transpose [B, Nn, H*64] -> [B, H, Nn, 64], optional L2 norm (clamped)
// ---------------------------------------------------------------------------
__global__ void qk_transnorm_kernel(const float* __restrict__ src,
                                    float* __restrict__ dst, int Nn, int do_norm)
{
    int gw = (int)((blockIdx.x * blockDim.x + threadIdx.x) >> 5);
    int lane = threadIdx.x & 31;
    int total = B * Nn * H;
    if (gw >= total) return;
    int h = gw % H;
    int n = (gw / H) % Nn;
    int b = gw / (H * Nn);
    const float* sp = src + (size_t)(b * Nn + n) * DIM + h * HD;
    float2 x = *(const float2*)(sp + lane * 2);
    float s = 1.f;
    if (do_norm) {
        float ss = x.x * x.x + x.y * x.y;
#pragma unroll
        for (int o = 16; o > 0; o >>= 1) ss += __shfl_xor_sync(0xffffffffu, ss, o);
        s = 1.0f / fmaxf(sqrtf(ss), 1e-12f);
    }
    float* dp = dst + (size_t)((b * H + h) * Nn + n) * HD;
    *(float2*)(dp + lane * 2) = make_float2(x.x * s, x.y * s);
}

// ---------------------------------------------------------------------------
// sim = q.k (beta_t=1); store fp32 sim and fp16 shifted A = exp(20*sim - 9).
// (R3-proven structure; only the A write changed.)
// ---------------------------------------------------------------------------
__global__ __launch_bounds__(256) void sim_kernel(
    const float* __restrict__ q, const float* __restrict__ k,
    float* __restrict__ simo, __half* __restrict__ Ao)
{
    __shared__ __align__(16) float Qs[64][68];
    __shared__ __align__(16) float Ks[64][68];
    int bh = blockIdx.z;
    int i0 = blockIdx.y * 64, j0 = blockIdx.x * 64;
    const float* qp = q + (size_t)bh * N1 * HD;
    const float* kp = k + (size_t)bh * N2 * HD;
    int tid = threadIdx.x;
    int tx = tid & 15, ty = tid >> 4;
    int lr = tid >> 2;
#pragma unroll
    for (int it = 0; it < 4; it++) {
        int lc = (((tid & 3) + (it << 2)) << 2);
        float4 qv = *(const float4*)(qp + (size_t)(i0 + lr) * HD + lc);
        Qs[lc + 0][lr] = qv.x; Qs[lc + 1][lr] = qv.y; Qs[lc + 2][lr] = qv.z; Qs[lc + 3][lr] = qv.w;
        float4 kv = *(const float4*)(kp + (size_t)(j0 + lr) * HD + lc);
        Ks[lc + 0][lr] = kv.x; Ks[lc + 1][lr] = kv.y; Ks[lc + 2][lr] = kv.z; Ks[lc + 3][lr] = kv.w;
    }
    __syncthreads();
    u64 acc2[4][2];
#pragma unroll
    for (int i = 0; i < 4; i++) { acc2[i][0] = 0ull; acc2[i][1] = 0ull; }
#pragma unroll 8
    for (int kk = 0; kk < 64; kk++) {
        float4 a = *(const float4*)&Qs[kk][ty << 2];
        float4 b = *(const float4*)&Ks[kk][tx << 2];
        u64 b01 = pack2(b.x, b.y), b23 = pack2(b.z, b.w);
        float av[4] = {a.x, a.y, a.z, a.w};
#pragma unroll
        for (int i = 0; i < 4; i++) {
            u64 ad = pack2(av[i], av[i]);
            acc2[i][0] = ffma2(ad, b01, acc2[i][0]);
            acc2[i][1] = ffma2(ad, b23, acc2[i][1]);
        }
    }
    size_t base = (size_t)bh * N1 * N2;
#pragma unroll
    for (int i = 0; i < 4; i++) {
        size_t idx = base + (size_t)(i0 + (ty << 2) + i) * N2 + (j0 + (tx << 2));
        float2 p0 = unpack2(acc2[i][0]);
        float2 p1 = unpack2(acc2[i][1]);
        *(float4*)(simo + idx) = make_float4(p0.x, p0.y, p1.x, p1.y);
        __half2* A2 = (__half2*)(Ao + idx);
        A2[0] = __floats2half2_rn(__expf(fmaf(p0.x, 20.0f, -9.0f)),
                                  __expf(fmaf(p0.y, 20.0f, -9.0f)));
        A2[1] = __floats2half2_rn(__expf(fmaf(p1.x, 20.0f, -9.0f)),
                                  __expf(fmaf(p1.y, 20.0f, -9.0f)));
    }
}

// ---------------------------------------------------------------------------
// Sinkhorn (scaled domain), fp16 shifted A, one CTA per bh slice, 512 threads.
// Single pass per iteration computes A.beta (rows) and A^T.alpha (cols)
// with the OLD (alpha,beta) -- algebraically identical to the reference
// (uniform scale e^11 of A is absorbed by scale-invariance of T).
// Early-exit when max relative change < 1e-5 (below output significance).
// ---------------------------------------------------------------------------
__global__ __launch_bounds__(512) void sinkhorn_kernel(
    const __half* __restrict__ A16, float* __restrict__ alpha_out,
    float* __restrict__ beta_out)
{
    __shared__ __align__(16) float s_alpha[N1];
    __shared__ __align__(16) float s_beta[N2];
    __shared__ __align__(16) float s_r[N1];
    __shared__ __align__(16) float s_cpart[16][N2];
    __shared__ float s_wmax[16];

    int bh = blockIdx.x;
    const u32* A = (const u32*)(A16 + (size_t)bh * N1 * N2);  // 288 u32 per row
    int tid = threadIdx.x, lane = tid & 31, w = tid >> 5;

    for (int i = tid; i < N1; i += 512) s_alpha[i] = 1.f;
    for (int j = tid; j < N2; j += 512) s_beta[j] = 1.f;
    __syncthreads();

    const float MU = 1.0f / 256.0f + 1e-8f;
    const float NU = 1.0f / 576.0f + 1e-8f;

#pragma unroll 1
    for (int it = 0; it < ITERS; it++) {
        u64 pb[9], pc[9];
        const u64* sb2 = (const u64*)s_beta;
#pragma unroll
        for (int t = 0; t < 9; t++) { pb[t] = sb2[lane + 32 * t]; pc[t] = 0ull; }

#pragma unroll 1
        for (int rr = 0; rr < 16; rr++) {
            int i = w * 16 + rr;
            float ai = s_alpha[i];
            u64 ad = pack2(ai, ai);
            u64 accr2 = 0ull;
            const u32* row = A + i * 288 + lane;
#pragma unroll
            for (int t = 0; t < 9; t++) {
                u32 x = row[32 * t];
                __half2 h2 = *reinterpret_cast<const __half2*>(&x);
                float2 f = __half22float2(h2);       // HW cvt handles subnormal tail
                u64 a2 = pack2(f.x, f.y);
                accr2 = ffma2(a2, pb[t], accr2);     // row sum   (A beta)
                pc[t] = ffma2(a2, ad, pc[t]);        // col parts (A^T alpha)
            }
            float2 ar = unpack2(accr2);
            float accr = ar.x + ar.y;
#pragma unroll
            for (int o = 16; o > 0; o >>= 1) accr += __shfl_xor_sync(0xffffffffu, accr, o);
            if (lane == 0) s_r[i] = accr;
        }
        u64* cp2 = (u64*)&s_cpart[w][0];
#pragma unroll
        for (int t = 0; t < 9; t++) cp2[lane + 32 * t] = pc[t];
        __syncthreads();

        float mx = 0.f;
        if (tid < N1) {
            float na = MU / s_r[tid];
            mx = fabsf(na - s_alpha[tid]) / na;
            s_alpha[tid] = na;
        }
        for (int j = tid; j < N2; j += 512) {
            float sc = 0.f;
#pragma unroll
            for (int ww = 0; ww < 16; ww++) sc += s_cpart[ww][j];
            float nb = NU / sc;
            mx = fmaxf(mx, fabsf(nb - s_beta[j]) / nb);
            s_beta[j] = nb;
        }
#pragma unroll
        for (int o = 16; o > 0; o >>= 1) mx = fmaxf(mx, __shfl_xor_sync(0xffffffffu, mx, o));
        if (lane == 0) s_wmax[w] = mx;
        __syncthreads();
        float m = 0.f;
#pragma unroll
        for (int ww = 0; ww < 16; ww++) m = fmaxf(m, s_wmax[ww]);
        if (m < 1e-5f) break;   // further iterations change output below rel-err floor
    }

    for (int i = tid; i < N1; i += 512) alpha_out[bh * N1 + i] = s_alpha[i];
    for (int j = tid; j < N2; j += 512) beta_out[bh * N2 + j] = s_beta[j];
}

// ---------------------------------------------------------------------------
// ctx = (N1*N2 * sim * exp(20*sim-9) * alpha_n * beta_m) @ v
// (fp32 A recomputed with the SAME shift as Sinkhorn's -> consistent T.)
// R3-proven structure.
// ---------------------------------------------------------------------------
__global__ __launch_bounds__(256) void av_kernel(
    const float* __restrict__ sim_all, const float* __restrict__ v_all,
    const float* __restrict__ alpha, const float* __restrict__ beta,
    float* __restrict__ ctx)
{
    __shared__ __align__(16) float Ss[64][68];   // [m][n]
    __shared__ __align__(16) float Vs[64][68];   // [m][c]
    __shared__ float sa[64];
    __shared__ float sb[64];
    int bh = blockIdx.y;
    int n0 = blockIdx.x * 64;
    const float* simp = sim_all + (size_t)bh * N1 * N2;
    const float* vp   = v_all   + (size_t)bh * N2 * HD;
    int tid = threadIdx.x, tx = tid & 15, ty = tid >> 4;
    int lr = tid >> 2;

    if (tid < 64) sa[tid] = alpha[bh * N1 + n0 + tid] * 147456.0f;  // fold N1*N2

    u64 acc2[4][2];
#pragma unroll
    for (int i = 0; i < 4; i++) { acc2[i][0] = 0ull; acc2[i][1] = 0ull; }

    for (int m0 = 0; m0 < N2; m0 += 64) {
        if (tid < 64) sb[tid] = beta[bh * N2 + m0 + tid];
        __syncthreads();          // guards sa/sb visible + previous compute done
#pragma unroll
        for (int it = 0; it < 4; it++) {
            int lc = (((tid & 3) + (it << 2)) << 2);
            size_t idx = (size_t)(n0 + lr) * N2 + m0 + lc;
            float4 sv = *(const float4*)(simp + idx);
            float an = sa[lr];
            Ss[lc + 0][lr] = sv.x * __expf(fmaf(sv.x, 20.f, -9.f)) * an * sb[lc + 0];
            Ss[lc + 1][lr] = sv.y * __expf(fmaf(sv.y, 20.f, -9.f)) * an * sb[lc + 1];
            Ss[lc + 2][lr] = sv.z * __expf(fmaf(sv.z, 20.f, -9.f)) * an * sb[lc + 2];
            Ss[lc + 3][lr] = sv.w * __expf(fmaf(sv.w, 20.f, -9.f)) * an * sb[lc + 3];
            float4 vv = *(const float4*)(vp + (size_t)(m0 + lr) * HD + lc);
            *(float4*)&Vs[lr][lc] = vv;
        }
        __syncthreads();
#pragma unroll 8
        for (int kk = 0; kk < 64; kk++) {
            float4 a = *(const float4*)&Ss[kk][ty << 2];
            float4 b = *(const float4*)&Vs[kk][tx << 2];
            u64 b01 = pack2(b.x, b.y), b23 = pack2(b.z, b.w);
            float av[4] = {a.x, a.y, a.z, a.w};
#pragma unroll
            for (int i = 0; i < 4; i++) {
                u64 ad = pack2(av[i], av[i]);
                acc2[i][0] = ffma2(ad, b01, acc2[i][0]);
                acc2[i][1] = ffma2(ad, b23, acc2[i][1]);
            }
        }
    }
    int b = bh >> 3, h = bh & 7;
#pragma unroll
    for (int i = 0; i < 4; i++) {
        float2 p0 = unpack2(acc2[i][0]);
        float2 p1 = unpack2(acc2[i][1]);
        float* dst = ctx + (size_t)(b * N1 + n0 + (ty << 2) + i) * DIM + h * HD + (tx << 2);
        *(float4*)dst = make_float4(p0.x, p0.y, p1.x, p1.y);
    }
}

// ---------------------------------------------------------------------------
// In-place row L2 normalization (plain divide): rows of 512 floats
// ---------------------------------------------------------------------------
__global__ __launch_bounds__(128) void norm_rows_kernel(float* __restrict__ out)
{
    __shared__ float red[4];
    int row = blockIdx.x;
    float4* p = (float4*)(out + (size_t)row * DIM);
    int tid = threadIdx.x;
    float4 v = p[tid];
    float ss = v.x * v.x + v.y * v.y + v.z * v.z + v.w * v.w;
#pragma unroll
    for (int o = 16; o > 0; o >>= 1) ss += __shfl_xor_sync(0xffffffffu, ss, o);
    if ((tid & 31) == 0) red[tid >> 5] = ss;
    __syncthreads();
    float tot = red[0] + red[1] + red[2] + red[3];
    float inv = 1.0f / sqrtf(tot);
    v.x *= inv; v.y *= inv; v.z *= inv; v.w *= inv;
    p[tid] = v;
}

// ---------------------------------------------------------------------------
extern "C" void kernel_launch(void* const* d_in, const int* in_sizes, int n_in,
                              void* d_out, int out_size)
{
    (void)in_sizes; (void)n_in; (void)out_size;
    const float* F_t = (const float*)d_in[0];
    const float* F_s = (const float*)d_in[1];
    const float* Wq  = (const float*)d_in[2];
    const float* bq  = (const float*)d_in[3];
    const float* Wk  = (const float*)d_in[4];
    const float* bk  = (const float*)d_in[5];
    const float* Wv  = (const float*)d_in[6];
    const float* bv  = (const float*)d_in[7];
    const float* Wp  = (const float*)d_in[8];
    const float* bp  = (const float*)d_in[9];
    float* out = (float*)d_out;

    float *tq, *tk, *tv, *q, *k, *v, *simb, *alpha, *beta, *ctx;
    __half* A16;
    cudaGetSymbolAddress((void**)&tq, g_tq);
    cudaGetSymbolAddress((void**)&tk, g_tk);
    cudaGetSymbolAddress((void**)&tv, g_tv);
    cudaGetSymbolAddress((void**)&q, g_q);
    cudaGetSymbolAddress((void**)&k, g_k);
    cudaGetSymbolAddress((void**)&v, g_v);
    cudaGetSymbolAddress((void**)&simb, g_sim);
    cudaGetSymbolAddress((void**)&A16, g_A16);
    cudaGetSymbolAddress((void**)&alpha, g_alpha);
    cudaGetSymbolAddress((void**)&beta, g_beta);
    cudaGetSymbolAddress((void**)&ctx, g_ctx);

    // 1) QKV projections (conv1d k=1 == pointwise linear), 128x128 FFMA2 GEMM
    gemm128_kernel<<<dim3(DIM / 128, B * N1 / 128), 256>>>(F_t, Wq, bq, tq, B * N1, DIM, DIM);
    gemm128_kernel<<<dim3(DIM / 128, B * N2 / 128), 256>>>(F_s, Wk, bk, tk, B * N2, DIM, DIM);
    gemm128_kernel<<<dim3(DIM / 128, B * N2 / 128), 256>>>(F_s, Wv, bv, tv, B * N2, DIM, DIM);

    // 2) transpose to [B,H,Nx,64] (+ l2norm for q,k)
    {
        int warps_q = B * N1 * H;
        int warps_k = B * N2 * H;
        qk_transnorm_kernel<<<(warps_q * 32 + 255) / 256, 256>>>(tq, q, N1, 1);
        qk_transnorm_kernel<<<(warps_k * 32 + 255) / 256, 256>>>(tk, k, N2, 1);
        qk_transnorm_kernel<<<(warps_k * 32 + 255) / 256, 256>>>(tv, v, N2, 0);
    }

    // 3) sim (fp32) + fp16 shifted Gibbs kernel A = exp(20*sim - 9)
    sim_kernel<<<dim3(N2 / 64, N1 / 64, BH), 256>>>(q, k, simb, A16);

    // 4) Sinkhorn iterations (fp16 A, early exit), one CTA per (b,h)
    sinkhorn_kernel<<<BH, 512>>>(A16, alpha, beta);

    // 5) score @ v -> ctx [B*N1, 512]  (fp32 shifted A recomputed from sim)
    av_kernel<<<dim3(N1 / 64, BH), 256>>>(simb, v, alpha, beta, ctx);

    // 6) projection + 7) row normalize (in place in d_out)
    gemm128_kernel<<<dim3(DIM / 128, B * N1 / 128), 256>>>(ctx, Wp, bp, out, B * N1, DIM, DIM);
    norm_rows_kernel<<<B * N1, 128>>>(out);
}

// round 6
// speedup vs baseline: 1.1939x; 1.0918x over previous
#include <cuda_runtime.h>
#include <cuda_fp16.h>
#include <math.h>

// Problem constants
constexpr int B   = 16;
constexpr int H   = 8;
constexpr int N1  = 256;
constexpr int N2  = 576;
constexpr int HD  = 64;
constexpr int DIM = 512;
constexpr int BH  = B * H;       // 128
constexpr int ITERS = 100;

typedef unsigned long long u64;
typedef unsigned int u32;

// ---- packed f32x2 helpers (sm_103a FFMA2; ptxas never auto-fuses) ----
__device__ __forceinline__ u64 ffma2(u64 a, u64 b, u64 c) {
    u64 d; asm("fma.rn.f32x2 %0,%1,%2,%3;" : "=l"(d) : "l"(a), "l"(b), "l"(c)); return d;
}
__device__ __forceinline__ u64 pack2(float x, float y) {
    u64 d; asm("mov.b64 %0,{%1,%2};" : "=l"(d) : "f"(x), "f"(y)); return d;
}
__device__ __forceinline__ float2 unpack2(u64 d) {
    float2 r; asm("mov.b64 {%0,%1},%2;" : "=f"(r.x), "=f"(r.y) : "l"(d)); return r;
}

// Static scratch (no runtime allocation allowed)
__device__ float g_q[BH * N1 * HD];
__device__ float g_k[BH * N2 * HD];
__device__ float g_v[BH * N2 * HD];
__device__ float g_sim[(size_t)BH * N1 * N2];     // fp32 sim (exact)
__device__ __half g_A16[(size_t)BH * N1 * N2];    // fp16 shifted Gibbs kernel e^(20 sim - 9)
__device__ float g_alpha[BH * N1];
__device__ float g_beta[BH * N2];
__device__ float g_ctx[B * N1 * DIM];

// ---------------------------------------------------------------------------
// fp32 GEMM, 128x128 tile, 256 threads, 8x8/thread, FFMA2 inner product.
// MODE 0: plain  out0[M,N] = X@W0^T + bias0
// MODE 1: q epilogue  — add bias, per-head (64-col quadrant) L2 norm,
//         scatter to [B,H,N1,64] layout in out0.
// MODE 2: kv epilogue — N=1024 logical; cols [0,512) from W0 (k, normalized,
//         -> out0), cols [512,1024) from W1 (v, raw -> out1), layout [B,H,N2,64].
// ---------------------------------------------------------------------------
template<int MODE>
__global__ __launch_bounds__(256) void gemm128_kernel(
    const float* __restrict__ X,
    const float* __restrict__ W0, const float* __restrict__ W1,
    const float* __restrict__ bias0, const float* __restrict__ bias1,
    float* __restrict__ out0, float* __restrict__ out1,
    int M, int N, int K)
{
    __shared__ __align__(16) float Xs[16][132];
    __shared__ __align__(16) float Ws[16][132];
    const int tid = threadIdx.x;
    const int tx = tid & 15, ty = tid >> 4;
    const int bm = blockIdx.y * 128, bn = blockIdx.x * 128;
    const int lr = tid >> 1;            // 0..127
    const int lc = (tid & 1) * 8;       // 0 or 8

    const float* Wsel;
    const float* bsel;
    if (MODE == 2 && bn >= 512) { Wsel = W1 + (size_t)(bn - 512) * K; bsel = bias1 + (bn - 512); }
    else                        { Wsel = W0 + (size_t)bn * K;         bsel = bias0 + bn; }

    u64 acc[2][2][4][2];
#pragma unroll
    for (int iq = 0; iq < 2; iq++)
#pragma unroll
        for (int jq = 0; jq < 2; jq++)
#pragma unroll
            for (int i = 0; i < 4; i++) { acc[iq][jq][i][0] = 0ull; acc[iq][jq][i][1] = 0ull; }

    const float* Xp = X + (size_t)(bm + lr) * K + lc;
    const float* Wp = Wsel + (size_t)lr * K + lc;

    for (int k0 = 0; k0 < K; k0 += 16) {
        float4 x0 = *(const float4*)(Xp + k0);
        float4 x1 = *(const float4*)(Xp + k0 + 4);
        float4 w0 = *(const float4*)(Wp + k0);
        float4 w1 = *(const float4*)(Wp + k0 + 4);
        Xs[lc + 0][lr] = x0.x; Xs[lc + 1][lr] = x0.y; Xs[lc + 2][lr] = x0.z; Xs[lc + 3][lr] = x0.w;
        Xs[lc + 4][lr] = x1.x; Xs[lc + 5][lr] = x1.y; Xs[lc + 6][lr] = x1.z; Xs[lc + 7][lr] = x1.w;
        Ws[lc + 0][lr] = w0.x; Ws[lc + 1][lr] = w0.y; Ws[lc + 2][lr] = w0.z; Ws[lc + 3][lr] = w0.w;
        Ws[lc + 4][lr] = w1.x; Ws[lc + 5][lr] = w1.y; Ws[lc + 6][lr] = w1.z; Ws[lc + 7][lr] = w1.w;
        __syncthreads();
#pragma unroll
        for (int kk = 0; kk < 16; kk++) {
            float4 a0 = *(const float4*)&Xs[kk][ty * 4];
            float4 a1 = *(const float4*)&Xs[kk][64 + ty * 4];
            float4 b0 = *(const float4*)&Ws[kk][tx * 4];
            float4 b1 = *(const float4*)&Ws[kk][64 + tx * 4];
            u64 bp[2][2] = {{pack2(b0.x, b0.y), pack2(b0.z, b0.w)},
                            {pack2(b1.x, b1.y), pack2(b1.z, b1.w)}};
            float av[2][4] = {{a0.x, a0.y, a0.z, a0.w}, {a1.x, a1.y, a1.z, a1.w}};
#pragma unroll
            for (int iq = 0; iq < 2; iq++)
#pragma unroll
                for (int i = 0; i < 4; i++) {
                    u64 ad = pack2(av[iq][i], av[iq][i]);
#pragma unroll
                    for (int jq = 0; jq < 2; jq++) {
                        acc[iq][jq][i][0] = ffma2(ad, bp[jq][0], acc[iq][jq][i][0]);
                        acc[iq][jq][i][1] = ffma2(ad, bp[jq][1], acc[iq][jq][i][1]);
                    }
                }
        }
        __syncthreads();
    }

    // bias for this thread's 8 columns (4 per quadrant), constant over rows
    float4 bb0 = *(const float4*)(bsel + (tx << 2));
    float4 bb1 = *(const float4*)(bsel + 64 + (tx << 2));

    if (MODE == 0) {
#pragma unroll
        for (int iq = 0; iq < 2; iq++)
#pragma unroll
            for (int i = 0; i < 4; i++) {
                int r = bm + iq * 64 + ty * 4 + i;
#pragma unroll
                for (int jq = 0; jq < 2; jq++) {
                    int c = bn + jq * 64 + (tx << 2);
                    float4 bb = jq ? bb1 : bb0;
                    float2 p0 = unpack2(acc[iq][jq][i][0]);
                    float2 p1 = unpack2(acc[iq][jq][i][1]);
                    *(float4*)(out0 + (size_t)r * N + c) =
                        make_float4(p0.x + bb.x, p0.y + bb.y, p1.x + bb.z, p1.y + bb.w);
                }
            }
    } else {
        const bool do_norm = (MODE == 1) || (bn < 512);
#pragma unroll
        for (int iq = 0; iq < 2; iq++)
#pragma unroll
            for (int i = 0; i < 4; i++) {
                int r = bm + iq * 64 + ty * 4 + i;
                int b, nn;
                if (MODE == 1) { b = r >> 8; nn = r & 255; }
                else           { b = r / N2; nn = r - b * N2; }
#pragma unroll
                for (int jq = 0; jq < 2; jq++) {
                    float4 bb = jq ? bb1 : bb0;
                    float2 p0 = unpack2(acc[iq][jq][i][0]);
                    float2 p1 = unpack2(acc[iq][jq][i][1]);
                    float v0 = p0.x + bb.x, v1 = p0.y + bb.y;
                    float v2 = p1.x + bb.z, v3 = p1.y + bb.w;
                    float s = 1.f;
                    if (do_norm) {
                        float ss = v0 * v0 + v1 * v1 + v2 * v2 + v3 * v3;
                        ss += __shfl_xor_sync(0xffffffffu, ss, 1);
                        ss += __shfl_xor_sync(0xffffffffu, ss, 2);
                        ss += __shfl_xor_sync(0xffffffffu, ss, 4);
                        ss += __shfl_xor_sync(0xffffffffu, ss, 8);
                        s = 1.0f / fmaxf(sqrtf(ss), 1e-12f);
                    }
                    int c0 = bn + jq * 64;
                    float* dst;
                    if (MODE == 1) {
                        int h = c0 >> 6;
                        dst = out0 + ((size_t)((b * H + h) * N1 + nn)) * 64 + (tx << 2);
                    } else if (c0 < 512) {
                        int h = c0 >> 6;
                        dst = out0 + ((size_t)((b * H + h) * N2 + nn)) * 64 + (tx << 2);
                    } else {
                        int h = (c0 - 512) >> 6;
                        dst = out1 + ((size_t)((b * H + h) * N2 + nn)) * 64 + (tx << 2);
                    }
                    *(float4*)dst = make_float4(v0 * s, v1 * s, v2 * s, v3 * s);
                }
            }
    }
}

// ---------------------------------------------------------------------------
// sim = q.k (beta_t=1); store fp32 sim and fp16 shifted A = exp(20*sim - 9).
// ---------------------------------------------------------------------------
__global__ __launch_bounds__(256) void sim_kernel(
    const float* __restrict__ q, const float* __restrict__ k,
    float* __restrict__ simo, __half* __restrict__ Ao)
{
    __shared__ __align__(16) float Qs[64][68];
    __shared__ __align__(16) float Ks[64][68];
    int bh = blockIdx.z;
    int i0 = blockIdx.y * 64, j0 = blockIdx.x * 64;
    const float* qp = q + (size_t)bh * N1 * HD;
    const float* kp = k + (size_t)bh * N2 * HD;
    int tid = threadIdx.x;
    int tx = tid & 15, ty = tid >> 4;
    int lr = tid >> 2;
#pragma unroll
    for (int it = 0; it < 4; it++) {
        int lc = (((tid & 3) + (it << 2)) << 2);
        float4 qv = *(const float4*)(qp + (size_t)(i0 + lr) * HD + lc);
        Qs[lc + 0][lr] = qv.x; Qs[lc + 1][lr] = qv.y; Qs[lc + 2][lr] = qv.z; Qs[lc + 3][lr] = qv.w;
        float4 kv = *(const float4*)(kp + (size_t)(j0 + lr) * HD + lc);
        Ks[lc + 0][lr] = kv.x; Ks[lc + 1][lr] = kv.y; Ks[lc + 2][lr] = kv.z; Ks[lc + 3][lr] = kv.w;
    }
    __syncthreads();
    u64 acc2[4][2];
#pragma unroll
    for (int i = 0; i < 4; i++) { acc2[i][0] = 0ull; acc2[i][1] = 0ull; }
#pragma unroll 8
    for (int kk = 0; kk < 64; kk++) {
        float4 a = *(const float4*)&Qs[kk][ty << 2];
        float4 b = *(const float4*)&Ks[kk][tx << 2];
        u64 b01 = pack2(b.x, b.y), b23 = pack2(b.z, b.w);
        float av[4] = {a.x, a.y, a.z, a.w};
#pragma unroll
        for (int i = 0; i < 4; i++) {
            u64 ad = pack2(av[i], av[i]);
            acc2[i][0] = ffma2(ad, b01, acc2[i][0]);
            acc2[i][1] = ffma2(ad, b23, acc2[i][1]);
        }
    }
    size_t base = (size_t)bh * N1 * N2;
#pragma unroll
    for (int i = 0; i < 4; i++) {
        size_t idx = base + (size_t)(i0 + (ty << 2) + i) * N2 + (j0 + (tx << 2));
        float2 p0 = unpack2(acc2[i][0]);
        float2 p1 = unpack2(acc2[i][1]);
        *(float4*)(simo + idx) = make_float4(p0.x, p0.y, p1.x, p1.y);
        __half2* A2 = (__half2*)(Ao + idx);
        A2[0] = __floats2half2_rn(__expf(fmaf(p0.x, 20.0f, -9.0f)),
                                  __expf(fmaf(p0.y, 20.0f, -9.0f)));
        A2[1] = __floats2half2_rn(__expf(fmaf(p1.x, 20.0f, -9.0f)),
                                  __expf(fmaf(p1.y, 20.0f, -9.0f)));
    }
}

// ---------------------------------------------------------------------------
// Sinkhorn (scaled domain), fp16 shifted A, one CTA per bh slice, 512 threads.
// Row loop unrolled x4: ~36 L2 loads in flight per warp, shfl trees of row i
// overlap loads of rows i+1..3. No convergence check (never fires).
// ---------------------------------------------------------------------------
__global__ __launch_bounds__(512) void sinkhorn_kernel(
    const __half* __restrict__ A16, float* __restrict__ alpha_out,
    float* __restrict__ beta_out)
{
    __shared__ __align__(16) float s_alpha[N1];
    __shared__ __align__(16) float s_beta[N2];
    __shared__ __align__(16) float s_r[N1];
    __shared__ __align__(16) float s_cpart[16][N2];

    int bh = blockIdx.x;
    const u32* A = (const u32*)(A16 + (size_t)bh * N1 * N2);  // 288 u32 per row
    int tid = threadIdx.x, lane = tid & 31, w = tid >> 5;

    for (int i = tid; i < N1; i += 512) s_alpha[i] = 1.f;
    for (int j = tid; j < N2; j += 512) s_beta[j] = 1.f;
    __syncthreads();

    const float MU = 1.0f / 256.0f + 1e-8f;
    const float NU = 1.0f / 576.0f + 1e-8f;

#pragma unroll 1
    for (int it = 0; it < ITERS; it++) {
        u64 pb[9], pc[9];
        const u64* sb2 = (const u64*)s_beta;
#pragma unroll
        for (int t = 0; t < 9; t++) { pb[t] = sb2[lane + 32 * t]; pc[t] = 0ull; }

#pragma unroll 4
        for (int rr = 0; rr < 16; rr++) {
            int i = w * 16 + rr;
            float ai = s_alpha[i];
            u64 ad = pack2(ai, ai);
            u64 accr2 = 0ull;
            const u32* row = A + i * 288 + lane;
#pragma unroll
            for (int t = 0; t < 9; t++) {
                u32 x = row[32 * t];
                __half2 h2 = *reinterpret_cast<const __half2*>(&x);
                float2 f = __half22float2(h2);       // HW cvt handles subnormal tail
                u64 a2 = pack2(f.x, f.y);
                accr2 = ffma2(a2, pb[t], accr2);     // row sum   (A beta)
                pc[t] = ffma2(a2, ad, pc[t]);        // col parts (A^T alpha)
            }
            float2 ar = unpack2(accr2);
            float accr = ar.x + ar.y;
#pragma unroll
            for (int o = 16; o > 0; o >>= 1) accr += __shfl_xor_sync(0xffffffffu, accr, o);
            if (lane == 0) s_r[i] = accr;
        }
        u64* cp2 = (u64*)&s_cpart[w][0];
#pragma unroll
        for (int t = 0; t < 9; t++) cp2[lane + 32 * t] = pc[t];
        __syncthreads();

        if (tid < N1) s_alpha[tid] = MU / s_r[tid];
        for (int j = tid; j < N2; j += 512) {
            float sc = 0.f;
#pragma unroll
            for (int ww = 0; ww < 16; ww++) sc += s_cpart[ww][j];
            s_beta[j] = NU / sc;
        }
        __syncthreads();
    }

    for (int i = tid; i < N1; i += 512) alpha_out[bh * N1 + i] = s_alpha[i];
    for (int j = tid; j < N2; j += 512) beta_out[bh * N2 + j] = s_beta[j];
}

// ---------------------------------------------------------------------------
// ctx = (N1*N2 * sim * exp(20*sim-9) * alpha_n * beta_m) @ v
// (fp32 A recomputed with the SAME shift as Sinkhorn's -> consistent T.)
// ---------------------------------------------------------------------------
__global__ __launch_bounds__(256) void av_kernel(
    const float* __restrict__ sim_all, const float* __restrict__ v_all,
    const float* __restrict__ alpha, const float* __restrict__ beta,
    float* __restrict__ ctx)
{
    __shared__ __align__(16) float Ss[64][68];   // [m][n]
    __shared__ __align__(16) float Vs[64][68];   // [m][c]
    __shared__ float sa[64];
    __shared__ float sb[64];
    int bh = blockIdx.y;
    int n0 = blockIdx.x * 64;
    const float* simp = sim_all + (size_t)bh * N1 * N2;
    const float* vp   = v_all   + (size_t)bh * N2 * HD;
    int tid = threadIdx.x, tx = tid & 15, ty = tid >> 4;
    int lr = tid >> 2;

    if (tid < 64) sa[tid] = alpha[bh * N1 + n0 + tid] * 147456.0f;  // fold N1*N2

    u64 acc2[4][2];
#pragma unroll
    for (int i = 0; i < 4; i++) { acc2[i][0] = 0ull; acc2[i][1] = 0ull; }

    for (int m0 = 0; m0 < N2; m0 += 64) {
        if (tid < 64) sb[tid] = beta[bh * N2 + m0 + tid];
        __syncthreads();          // guards sa/sb visible + previous compute done
#pragma unroll
        for (int it = 0; it < 4; it++) {
            int lc = (((tid & 3) + (it << 2)) << 2);
            size_t idx = (size_t)(n0 + lr) * N2 + m0 + lc;
            float4 sv = *(const float4*)(simp + idx);
            float an = sa[lr];
            Ss[lc + 0][lr] = sv.x * __expf(fmaf(sv.x, 20.f, -9.f)) * an * sb[lc + 0];
            Ss[lc + 1][lr] = sv.y * __expf(fmaf(sv.y, 20.f, -9.f)) * an * sb[lc + 1];
            Ss[lc + 2][lr] = sv.z * __expf(fmaf(sv.z, 20.f, -9.f)) * an * sb[lc + 2];
            Ss[lc + 3][lr] = sv.w * __expf(fmaf(sv.w, 20.f, -9.f)) * an * sb[lc + 3];
            float4 vv = *(const float4*)(vp + (size_t)(m0 + lr) * HD + lc);
            *(float4*)&Vs[lr][lc] = vv;
        }
        __syncthreads();
#pragma unroll 8
        for (int kk = 0; kk < 64; kk++) {
            float4 a = *(const float4*)&Ss[kk][ty << 2];
            float4 b = *(const float4*)&Vs[kk][tx << 2];
            u64 b01 = pack2(b.x, b.y), b23 = pack2(b.z, b.w);
            float av[4] = {a.x, a.y, a.z, a.w};
#pragma unroll
            for (int i = 0; i < 4; i++) {
                u64 ad = pack2(av[i], av[i]);
                acc2[i][0] = ffma2(ad, b01, acc2[i][0]);
                acc2[i][1] = ffma2(ad, b23, acc2[i][1]);
            }
        }
    }
    int b = bh >> 3, h = bh & 7;
#pragma unroll
    for (int i = 0; i < 4; i++) {
        float2 p0 = unpack2(acc2[i][0]);
        float2 p1 = unpack2(acc2[i][1]);
        float* dst = ctx + (size_t)(b * N1 + n0 + (ty << 2) + i) * DIM + h * HD + (tx << 2);
        *(float4*)dst = make_float4(p0.x, p0.y, p1.x, p1.y);
    }
}

// ---------------------------------------------------------------------------
// In-place row L2 normalization (plain divide): rows of 512 floats
// ---------------------------------------------------------------------------
__global__ __launch_bounds__(128) void norm_rows_kernel(float* __restrict__ out)
{
    __shared__ float red[4];
    int row = blockIdx.x;
    float4* p = (float4*)(out + (size_t)row * DIM);
    int tid = threadIdx.x;
    float4 v = p[tid];
    float ss = v.x * v.x + v.y * v.y + v.z * v.z + v.w * v.w;
#pragma unroll
    for (int o = 16; o > 0; o >>= 1) ss += __shfl_xor_sync(0xffffffffu, ss, o);
    if ((tid & 31) == 0) red[tid >> 5] = ss;
    __syncthreads();
    float tot = red[0] + red[1] + red[2] + red[3];
    float inv = 1.0f / sqrtf(tot);
    v.x *= inv; v.y *= inv; v.z *= inv; v.w *= inv;
    p[tid] = v;
}

// ---------------------------------------------------------------------------
extern "C" void kernel_launch(void* const* d_in, const int* in_sizes, int n_in,
                              void* d_out, int out_size)
{
    (void)in_sizes; (void)n_in; (void)out_size;
    const float* F_t = (const float*)d_in[0];
    const float* F_s = (const float*)d_in[1];
    const float* Wq  = (const float*)d_in[2];
    const float* bq  = (const float*)d_in[3];
    const float* Wk  = (const float*)d_in[4];
    const float* bk  = (const float*)d_in[5];
    const float* Wv  = (const float*)d_in[6];
    const float* bv  = (const float*)d_in[7];
    const float* Wp  = (const float*)d_in[8];
    const float* bp  = (const float*)d_in[9];
    float* out = (float*)d_out;

    float *q, *k, *v, *simb, *alpha, *beta, *ctx;
    __half* A16;
    cudaGetSymbolAddress((void**)&q, g_q);
    cudaGetSymbolAddress((void**)&k, g_k);
    cudaGetSymbolAddress((void**)&v, g_v);
    cudaGetSymbolAddress((void**)&simb, g_sim);
    cudaGetSymbolAddress((void**)&A16, g_A16);
    cudaGetSymbolAddress((void**)&alpha, g_alpha);
    cudaGetSymbolAddress((void**)&beta, g_beta);
    cudaGetSymbolAddress((void**)&ctx, g_ctx);

    // 1) Q projection fused with transpose + per-head l2norm  -> g_q [B,H,N1,64]
    gemm128_kernel<1><<<dim3(DIM / 128, B * N1 / 128), 256>>>(
        F_t, Wq, nullptr, bq, nullptr, q, nullptr, B * N1, DIM, DIM);

    // 2) K+V fused projection (N=1024) with transpose (+norm for K)
    gemm128_kernel<2><<<dim3(1024 / 128, B * N2 / 128), 256>>>(
        F_s, Wk, Wv, bk, bv, k, v, B * N2, 1024, DIM);

    // 3) sim (fp32) + fp16 shifted Gibbs kernel A = exp(20*sim - 9)
    sim_kernel<<<dim3(N2 / 64, N1 / 64, BH), 256>>>(q, k, simb, A16);

    // 4) 100 Sinkhorn iterations (fp16 A), one CTA per (b,h)
    sinkhorn_kernel<<<BH, 512>>>(A16, alpha, beta);

    // 5) score @ v -> ctx [B*N1, 512]  (fp32 shifted A recomputed from sim)
    av_kernel<<<dim3(N1 / 64, BH), 256>>>(simb, v, alpha, beta, ctx);

    // 6) projection + 7) row normalize (in place in d_out)
    gemm128_kernel<0><<<dim3(DIM / 128, B * N1 / 128), 256>>>(
        ctx, Wp, nullptr, bp, nullptr, out, nullptr, B * N1, DIM, DIM);
    norm_rows_kernel<<<B * N1, 128>>>(out);
}

// round 7
// speedup vs baseline: 1.4693x; 1.2306x over previous
#include <cuda_runtime.h>
#include <cuda_fp16.h>
#include <math.h>

// Problem constants
constexpr int B   = 16;
constexpr int H   = 8;
constexpr int N1  = 256;
constexpr int N2  = 576;
constexpr int HD  = 64;
constexpr int DIM = 512;
constexpr int BH  = B * H;       // 128
constexpr int ITERS = 100;

typedef unsigned long long u64;
typedef unsigned int u32;

// ---- packed f32x2 helpers (sm_103a FFMA2; ptxas never auto-fuses) ----
__device__ __forceinline__ u64 ffma2(u64 a, u64 b, u64 c) {
    u64 d; asm("fma.rn.f32x2 %0,%1,%2,%3;" : "=l"(d) : "l"(a), "l"(b), "l"(c)); return d;
}
__device__ __forceinline__ u64 pack2(float x, float y) {
    u64 d; asm("mov.b64 %0,{%1,%2};" : "=l"(d) : "f"(x), "f"(y)); return d;
}
__device__ __forceinline__ float2 unpack2(u64 d) {
    float2 r; asm("mov.b64 {%0,%1},%2;" : "=f"(r.x), "=f"(r.y) : "l"(d)); return r;
}

// Static scratch (no runtime allocation allowed)
__device__ float g_q[BH * N1 * HD];
__device__ float g_k[BH * N2 * HD];
__device__ float g_v[BH * N2 * HD];
__device__ float g_sim[(size_t)BH * N1 * N2];     // fp32 sim (exact)
__device__ __half g_A16[(size_t)BH * N1 * N2];    // fp16 shifted Gibbs kernel e^(20 sim - 9)
__device__ float g_alpha[BH * N1];
__device__ float g_beta[BH * N2];
__device__ float g_ctx[B * N1 * DIM];

// ---------------------------------------------------------------------------
// fp32 GEMM, 128x128 tile, 256 threads, 8x8/thread, FFMA2 inner product.
// MODE 0: plain  out0[M,N] = X@W0^T + bias0
// MODE 1: q epilogue  — add bias, per-head (64-col quadrant) L2 norm,
//         scatter to [B,H,N1,64] layout in out0.
// MODE 2: kv epilogue — N=1024 logical; cols [0,512) from W0 (k, normalized,
//         -> out0), cols [512,1024) from W1 (v, raw -> out1), layout [B,H,N2,64].
// ---------------------------------------------------------------------------
template<int MODE>
__global__ __launch_bounds__(256) void gemm128_kernel(
    const float* __restrict__ X,
    const float* __restrict__ W0, const float* __restrict__ W1,
    const float* __restrict__ bias0, const float* __restrict__ bias1,
    float* __restrict__ out0, float* __restrict__ out1,
    int M, int N, int K)
{
    __shared__ __align__(16) float Xs[16][132];
    __shared__ __align__(16) float Ws[16][132];
    const int tid = threadIdx.x;
    const int tx = tid & 15, ty = tid >> 4;
    const int bm = blockIdx.y * 128, bn = blockIdx.x * 128;
    const int lr = tid >> 1;            // 0..127
    const int lc = (tid & 1) * 8;       // 0 or 8

    const float* Wsel;
    const float* bsel;
    if (MODE == 2 && bn >= 512) { Wsel = W1 + (size_t)(bn - 512) * K; bsel = bias1 + (bn - 512); }
    else                        { Wsel = W0 + (size_t)bn * K;         bsel = bias0 + bn; }

    u64 acc[2][2][4][2];
#pragma unroll
    for (int iq = 0; iq < 2; iq++)
#pragma unroll
        for (int jq = 0; jq < 2; jq++)
#pragma unroll
            for (int i = 0; i < 4; i++) { acc[iq][jq][i][0] = 0ull; acc[iq][jq][i][1] = 0ull; }

    const float* Xp = X + (size_t)(bm + lr) * K + lc;
    const float* Wp = Wsel + (size_t)lr * K + lc;

    for (int k0 = 0; k0 < K; k0 += 16) {
        float4 x0 = *(const float4*)(Xp + k0);
        float4 x1 = *(const float4*)(Xp + k0 + 4);
        float4 w0 = *(const float4*)(Wp + k0);
        float4 w1 = *(const float4*)(Wp + k0 + 4);
        Xs[lc + 0][lr] = x0.x; Xs[lc + 1][lr] = x0.y; Xs[lc + 2][lr] = x0.z; Xs[lc + 3][lr] = x0.w;
        Xs[lc + 4][lr] = x1.x; Xs[lc + 5][lr] = x1.y; Xs[lc + 6][lr] = x1.z; Xs[lc + 7][lr] = x1.w;
        Ws[lc + 0][lr] = w0.x; Ws[lc + 1][lr] = w0.y; Ws[lc + 2][lr] = w0.z; Ws[lc + 3][lr] = w0.w;
        Ws[lc + 4][lr] = w1.x; Ws[lc + 5][lr] = w1.y; Ws[lc + 6][lr] = w1.z; Ws[lc + 7][lr] = w1.w;
        __syncthreads();
#pragma unroll
        for (int kk = 0; kk < 16; kk++) {
            float4 a0 = *(const float4*)&Xs[kk][ty * 4];
            float4 a1 = *(const float4*)&Xs[kk][64 + ty * 4];
            float4 b0 = *(const float4*)&Ws[kk][tx * 4];
            float4 b1 = *(const float4*)&Ws[kk][64 + tx * 4];
            u64 bp[2][2] = {{pack2(b0.x, b0.y), pack2(b0.z, b0.w)},
                            {pack2(b1.x, b1.y), pack2(b1.z, b1.w)}};
            float av[2][4] = {{a0.x, a0.y, a0.z, a0.w}, {a1.x, a1.y, a1.z, a1.w}};
#pragma unroll
            for (int iq = 0; iq < 2; iq++)
#pragma unroll
                for (int i = 0; i < 4; i++) {
                    u64 ad = pack2(av[iq][i], av[iq][i]);
#pragma unroll
                    for (int jq = 0; jq < 2; jq++) {
                        acc[iq][jq][i][0] = ffma2(ad, bp[jq][0], acc[iq][jq][i][0]);
                        acc[iq][jq][i][1] = ffma2(ad, bp[jq][1], acc[iq][jq][i][1]);
                    }
                }
        }
        __syncthreads();
    }

    float4 bb0 = *(const float4*)(bsel + (tx << 2));
    float4 bb1 = *(const float4*)(bsel + 64 + (tx << 2));

    if (MODE == 0) {
#pragma unroll
        for (int iq = 0; iq < 2; iq++)
#pragma unroll
            for (int i = 0; i < 4; i++) {
                int r = bm + iq * 64 + ty * 4 + i;
#pragma unroll
                for (int jq = 0; jq < 2; jq++) {
                    int c = bn + jq * 64 + (tx << 2);
                    float4 bb = jq ? bb1 : bb0;
                    float2 p0 = unpack2(acc[iq][jq][i][0]);
                    float2 p1 = unpack2(acc[iq][jq][i][1]);
                    *(float4*)(out0 + (size_t)r * N + c) =
                        make_float4(p0.x + bb.x, p0.y + bb.y, p1.x + bb.z, p1.y + bb.w);
                }
            }
    } else {
        const bool do_norm = (MODE == 1) || (bn < 512);
#pragma unroll
        for (int iq = 0; iq < 2; iq++)
#pragma unroll
            for (int i = 0; i < 4; i++) {
                int r = bm + iq * 64 + ty * 4 + i;
                int b, nn;
                if (MODE == 1) { b = r >> 8; nn = r & 255; }
                else           { b = r / N2; nn = r - b * N2; }
#pragma unroll
                for (int jq = 0; jq < 2; jq++) {
                    float4 bb = jq ? bb1 : bb0;
                    float2 p0 = unpack2(acc[iq][jq][i][0]);
                    float2 p1 = unpack2(acc[iq][jq][i][1]);
                    float v0 = p0.x + bb.x, v1 = p0.y + bb.y;
                    float v2 = p1.x + bb.z, v3 = p1.y + bb.w;
                    float s = 1.f;
                    if (do_norm) {
                        float ss = v0 * v0 + v1 * v1 + v2 * v2 + v3 * v3;
                        ss += __shfl_xor_sync(0xffffffffu, ss, 1);
                        ss += __shfl_xor_sync(0xffffffffu, ss, 2);
                        ss += __shfl_xor_sync(0xffffffffu, ss, 4);
                        ss += __shfl_xor_sync(0xffffffffu, ss, 8);
                        s = 1.0f / fmaxf(sqrtf(ss), 1e-12f);
                    }
                    int c0 = bn + jq * 64;
                    float* dst;
                    if (MODE == 1) {
                        int h = c0 >> 6;
                        dst = out0 + ((size_t)((b * H + h) * N1 + nn)) * 64 + (tx << 2);
                    } else if (c0 < 512) {
                        int h = c0 >> 6;
                        dst = out0 + ((size_t)((b * H + h) * N2 + nn)) * 64 + (tx << 2);
                    } else {
                        int h = (c0 - 512) >> 6;
                        dst = out1 + ((size_t)((b * H + h) * N2 + nn)) * 64 + (tx << 2);
                    }
                    *(float4*)dst = make_float4(v0 * s, v1 * s, v2 * s, v3 * s);
                }
            }
    }
}

// ---------------------------------------------------------------------------
// sim = q.k (beta_t=1); store fp32 sim and fp16 shifted A = exp(20*sim - 9).
// ---------------------------------------------------------------------------
__global__ __launch_bounds__(256) void sim_kernel(
    const float* __restrict__ q, const float* __restrict__ k,
    float* __restrict__ simo, __half* __restrict__ Ao)
{
    __shared__ __align__(16) float Qs[64][68];
    __shared__ __align__(16) float Ks[64][68];
    int bh = blockIdx.z;
    int i0 = blockIdx.y * 64, j0 = blockIdx.x * 64;
    const float* qp = q + (size_t)bh * N1 * HD;
    const float* kp = k + (size_t)bh * N2 * HD;
    int tid = threadIdx.x;
    int tx = tid & 15, ty = tid >> 4;
    int lr = tid >> 2;
#pragma unroll
    for (int it = 0; it < 4; it++) {
        int lc = (((tid & 3) + (it << 2)) << 2);
        float4 qv = *(const float4*)(qp + (size_t)(i0 + lr) * HD + lc);
        Qs[lc + 0][lr] = qv.x; Qs[lc + 1][lr] = qv.y; Qs[lc + 2][lr] = qv.z; Qs[lc + 3][lr] = qv.w;
        float4 kv = *(const float4*)(kp + (size_t)(j0 + lr) * HD + lc);
        Ks[lc + 0][lr] = kv.x; Ks[lc + 1][lr] = kv.y; Ks[lc + 2][lr] = kv.z; Ks[lc + 3][lr] = kv.w;
    }
    __syncthreads();
    u64 acc2[4][2];
#pragma unroll
    for (int i = 0; i < 4; i++) { acc2[i][0] = 0ull; acc2[i][1] = 0ull; }
#pragma unroll 8
    for (int kk = 0; kk < 64; kk++) {
        float4 a = *(const float4*)&Qs[kk][ty << 2];
        float4 b = *(const float4*)&Ks[kk][tx << 2];
        u64 b01 = pack2(b.x, b.y), b23 = pack2(b.z, b.w);
        float av[4] = {a.x, a.y, a.z, a.w};
#pragma unroll
        for (int i = 0; i < 4; i++) {
            u64 ad = pack2(av[i], av[i]);
            acc2[i][0] = ffma2(ad, b01, acc2[i][0]);
            acc2[i][1] = ffma2(ad, b23, acc2[i][1]);
        }
    }
    size_t base = (size_t)bh * N1 * N2;
#pragma unroll
    for (int i = 0; i < 4; i++) {
        size_t idx = base + (size_t)(i0 + (ty << 2) + i) * N2 + (j0 + (tx << 2));
        float2 p0 = unpack2(acc2[i][0]);
        float2 p1 = unpack2(acc2[i][1]);
        *(float4*)(simo + idx) = make_float4(p0.x, p0.y, p1.x, p1.y);
        __half2* A2 = (__half2*)(Ao + idx);
        A2[0] = __floats2half2_rn(__expf(fmaf(p0.x, 20.0f, -9.0f)),
                                  __expf(fmaf(p0.y, 20.0f, -9.0f)));
        A2[1] = __floats2half2_rn(__expf(fmaf(p1.x, 20.0f, -9.0f)),
                                  __expf(fmaf(p1.y, 20.0f, -9.0f)));
    }
}

// ---------------------------------------------------------------------------
// Sinkhorn, fp16 shifted A, ONE CTA of 1024 threads (32 warps) per bh slice.
// Grid(128) < SM count -> 1 CTA/SM regardless; use the whole SM: 32 warps
// (8 rows each) to cover L2/shfl latency; dynamic smem for the 32-warp
// column-partial matrix (~77KB > 48KB static limit).
// ---------------------------------------------------------------------------
constexpr int SK_THREADS = 1024;
constexpr int SK_NW = SK_THREADS / 32;          // 32 warps
constexpr int SK_RPW = N1 / SK_NW;              // 8 rows per warp
constexpr int SK_CP_STRIDE = 584;               // padded col-partial stride
// float layout in dynamic smem:
constexpr int SK_OFF_ALPHA = 0;                 // [256]
constexpr int SK_OFF_R     = 256;               // [256]
constexpr int SK_OFF_BETA  = 512;               // [576] (8B aligned: 2048B)
constexpr int SK_OFF_CP    = 1088;              // [32][584]
constexpr int SK_SMEM_FLOATS = SK_OFF_CP + SK_NW * SK_CP_STRIDE;
constexpr int SK_SMEM_BYTES  = SK_SMEM_FLOATS * 4;   // ~79KB

__global__ __launch_bounds__(SK_THREADS, 1) void sinkhorn_kernel(
    const __half* __restrict__ A16, float* __restrict__ alpha_out,
    float* __restrict__ beta_out)
{
    extern __shared__ __align__(16) float smem[];
    float* s_alpha = smem + SK_OFF_ALPHA;
    float* s_r     = smem + SK_OFF_R;
    float* s_beta  = smem + SK_OFF_BETA;
    float* s_cpart = smem + SK_OFF_CP;

    int bh = blockIdx.x;
    const u32* A = (const u32*)(A16 + (size_t)bh * N1 * N2);  // 288 u32 per row
    int tid = threadIdx.x, lane = tid & 31, w = tid >> 5;

    for (int i = tid; i < N1; i += SK_THREADS) s_alpha[i] = 1.f;
    for (int j = tid; j < N2; j += SK_THREADS) s_beta[j] = 1.f;
    __syncthreads();

    const float MU = 1.0f / 256.0f + 1e-8f;
    const float NU = 1.0f / 576.0f + 1e-8f;

#pragma unroll 1
    for (int it = 0; it < ITERS; it++) {
        u64 pb[9], pc[9];
        const u64* sb2 = (const u64*)s_beta;
#pragma unroll
        for (int t = 0; t < 9; t++) { pb[t] = sb2[lane + 32 * t]; pc[t] = 0ull; }

#pragma unroll 4
        for (int rr = 0; rr < SK_RPW; rr++) {
            int i = w * SK_RPW + rr;
            float ai = s_alpha[i];
            u64 ad = pack2(ai, ai);
            u64 accr2 = 0ull;
            const u32* row = A + i * 288 + lane;
#pragma unroll
            for (int t = 0; t < 9; t++) {
                u32 x = row[32 * t];
                __half2 h2 = *reinterpret_cast<const __half2*>(&x);
                float2 f = __half22float2(h2);       // HW cvt handles subnormal tail
                u64 a2 = pack2(f.x, f.y);
                accr2 = ffma2(a2, pb[t], accr2);     // row sum   (A beta)
                pc[t] = ffma2(a2, ad, pc[t]);        // col parts (A^T alpha)
            }
            float2 ar = unpack2(accr2);
            float accr = ar.x + ar.y;
#pragma unroll
            for (int o = 16; o > 0; o >>= 1) accr += __shfl_xor_sync(0xffffffffu, accr, o);
            if (lane == 0) s_r[i] = accr;
        }
        u64* cp2 = (u64*)(s_cpart + w * SK_CP_STRIDE);
#pragma unroll
        for (int t = 0; t < 9; t++) cp2[lane + 32 * t] = pc[t];
        __syncthreads();

        if (tid < N1) s_alpha[tid] = MU / s_r[tid];
        if (tid < N2) {
            float sc = 0.f;
#pragma unroll
            for (int ww = 0; ww < SK_NW; ww++) sc += s_cpart[ww * SK_CP_STRIDE + tid];
            s_beta[tid] = NU / sc;
        }
        __syncthreads();
    }

    for (int i = tid; i < N1; i += SK_THREADS) alpha_out[bh * N1 + i] = s_alpha[i];
    for (int j = tid; j < N2; j += SK_THREADS) beta_out[bh * N2 + j] = s_beta[j];
}

// ---------------------------------------------------------------------------
// ctx = (N1*N2 * sim * exp(20*sim-9) * alpha_n * beta_m) @ v
// (fp32 A recomputed with the SAME shift as Sinkhorn's -> consistent T.)
// ---------------------------------------------------------------------------
__global__ __launch_bounds__(256) void av_kernel(
    const float* __restrict__ sim_all, const float* __restrict__ v_all,
    const float* __restrict__ alpha, const float* __restrict__ beta,
    float* __restrict__ ctx)
{
    __shared__ __align__(16) float Ss[64][68];   // [m][n]
    __shared__ __align__(16) float Vs[64][68];   // [m][c]
    __shared__ float sa[64];
    __shared__ float sb[64];
    int bh = blockIdx.y;
    int n0 = blockIdx.x * 64;
    const float* simp = sim_all + (size_t)bh * N1 * N2;
    const float* vp   = v_all   + (size_t)bh * N2 * HD;
    int tid = threadIdx.x, tx = tid & 15, ty = tid >> 4;
    int lr = tid >> 2;

    if (tid < 64) sa[tid] = alpha[bh * N1 + n0 + tid] * 147456.0f;  // fold N1*N2

    u64 acc2[4][2];
#pragma unroll
    for (int i = 0; i < 4; i++) { acc2[i][0] = 0ull; acc2[i][1] = 0ull; }

    for (int m0 = 0; m0 < N2; m0 += 64) {
        if (tid < 64) sb[tid] = beta[bh * N2 + m0 + tid];
        __syncthreads();          // guards sa/sb visible + previous compute done
#pragma unroll
        for (int it = 0; it < 4; it++) {
            int lc = (((tid & 3) + (it << 2)) << 2);
            size_t idx = (size_t)(n0 + lr) * N2 + m0 + lc;
            float4 sv = *(const float4*)(simp + idx);
            float an = sa[lr];
            Ss[lc + 0][lr] = sv.x * __expf(fmaf(sv.x, 20.f, -9.f)) * an * sb[lc + 0];
            Ss[lc + 1][lr] = sv.y * __expf(fmaf(sv.y, 20.f, -9.f)) * an * sb[lc + 1];
            Ss[lc + 2][lr] = sv.z * __expf(fmaf(sv.z, 20.f, -9.f)) * an * sb[lc + 2];
            Ss[lc + 3][lr] = sv.w * __expf(fmaf(sv.w, 20.f, -9.f)) * an * sb[lc + 3];
            float4 vv = *(const float4*)(vp + (size_t)(m0 + lr) * HD + lc);
            *(float4*)&Vs[lr][lc] = vv;
        }
        __syncthreads();
#pragma unroll 8
        for (int kk = 0; kk < 64; kk++) {
            float4 a = *(const float4*)&Ss[kk][ty << 2];
            float4 b = *(const float4*)&Vs[kk][tx << 2];
            u64 b01 = pack2(b.x, b.y), b23 = pack2(b.z, b.w);
            float av[4] = {a.x, a.y, a.z, a.w};
#pragma unroll
            for (int i = 0; i < 4; i++) {
                u64 ad = pack2(av[i], av[i]);
                acc2[i][0] = ffma2(ad, b01, acc2[i][0]);
                acc2[i][1] = ffma2(ad, b23, acc2[i][1]);
            }
        }
    }
    int b = bh >> 3, h = bh & 7;
#pragma unroll
    for (int i = 0; i < 4; i++) {
        float2 p0 = unpack2(acc2[i][0]);
        float2 p1 = unpack2(acc2[i][1]);
        float* dst = ctx + (size_t)(b * N1 + n0 + (ty << 2) + i) * DIM + h * HD + (tx << 2);
        *(float4*)dst = make_float4(p0.x, p0.y, p1.x, p1.y);
    }
}

// ---------------------------------------------------------------------------
// In-place row L2 normalization (plain divide): rows of 512 floats
// ---------------------------------------------------------------------------
__global__ __launch_bounds__(128) void norm_rows_kernel(float* __restrict__ out)
{
    __shared__ float red[4];
    int row = blockIdx.x;
    float4* p = (float4*)(out + (size_t)row * DIM);
    int tid = threadIdx.x;
    float4 v = p[tid];
    float ss = v.x * v.x + v.y * v.y + v.z * v.z + v.w * v.w;
#pragma unroll
    for (int o = 16; o > 0; o >>= 1) ss += __shfl_xor_sync(0xffffffffu, ss, o);
    if ((tid & 31) == 0) red[tid >> 5] = ss;
    __syncthreads();
    float tot = red[0] + red[1] + red[2] + red[3];
    float inv = 1.0f / sqrtf(tot);
    v.x *= inv; v.y *= inv; v.z *= inv; v.w *= inv;
    p[tid] = v;
}

// ---------------------------------------------------------------------------
extern "C" void kernel_launch(void* const* d_in, const int* in_sizes, int n_in,
                              void* d_out, int out_size)
{
    (void)in_sizes; (void)n_in; (void)out_size;
    const float* F_t = (const float*)d_in[0];
    const float* F_s = (const float*)d_in[1];
    const float* Wq  = (const float*)d_in[2];
    const float* bq  = (const float*)d_in[3];
    const float* Wk  = (const float*)d_in[4];
    const float* bk  = (const float*)d_in[5];
    const float* Wv  = (const float*)d_in[6];
    const float* bv  = (const float*)d_in[7];
    const float* Wp  = (const float*)d_in[8];
    const float* bp  = (const float*)d_in[9];
    float* out = (float*)d_out;

    float *q, *k, *v, *simb, *alpha, *beta, *ctx;
    __half* A16;
    cudaGetSymbolAddress((void**)&q, g_q);
    cudaGetSymbolAddress((void**)&k, g_k);
    cudaGetSymbolAddress((void**)&v, g_v);
    cudaGetSymbolAddress((void**)&simb, g_sim);
    cudaGetSymbolAddress((void**)&A16, g_A16);
    cudaGetSymbolAddress((void**)&alpha, g_alpha);
    cudaGetSymbolAddress((void**)&beta, g_beta);
    cudaGetSymbolAddress((void**)&ctx, g_ctx);

    // allow ~79KB dynamic smem for the 32-warp sinkhorn (attribute set, not alloc)
    cudaFuncSetAttribute(sinkhorn_kernel,
                         cudaFuncAttributeMaxDynamicSharedMemorySize, SK_SMEM_BYTES);

    // 1) Q projection fused with transpose + per-head l2norm  -> g_q [B,H,N1,64]
    gemm128_kernel<1><<<dim3(DIM / 128, B * N1 / 128), 256>>>(
        F_t, Wq, nullptr, bq, nullptr, q, nullptr, B * N1, DIM, DIM);

    // 2) K+V fused projection (N=1024) with transpose (+norm for K)
    gemm128_kernel<2><<<dim3(1024 / 128, B * N2 / 128), 256>>>(
        F_s, Wk, Wv, bk, bv, k, v, B * N2, 1024, DIM);

    // 3) sim (fp32) + fp16 shifted Gibbs kernel A = exp(20*sim - 9)
    sim_kernel<<<dim3(N2 / 64, N1 / 64, BH), 256>>>(q, k, simb, A16);

    // 4) 100 Sinkhorn iterations (fp16 A), one 1024-thread CTA per (b,h)
    sinkhorn_kernel<<<BH, SK_THREADS, SK_SMEM_BYTES>>>(A16, alpha, beta);

    // 5) score @ v -> ctx [B*N1, 512]  (fp32 shifted A recomputed from sim)
    av_kernel<<<dim3(N1 / 64, BH), 256>>>(simb, v, alpha, beta, ctx);

    // 6) projection + 7) row normalize (in place in d_out)
    gemm128_kernel<0><<<dim3(DIM / 128, B * N1 / 128), 256>>>(
        ctx, Wp, nullptr, bp, nullptr, out, nullptr, B * N1, DIM, DIM);
    norm_rows_kernel<<<B * N1, 128>>>(out);
}